// round 10
// baseline (speedup 1.0000x reference)
#include <cuda_runtime.h>
#include <cuda_bf16.h>
#include <cstddef>
#include <cstdint>

// Problem constants (B=16, T=2048, D=256, WINDOW=128)
#define BB 16
#define TT 2048
#define DD 256
#define WIN 128
#define BT (BB*TT)          // 32768
#define QKV_LD 768
#define PADT 2432
#define KBAND 384

// ---------------- scratch (__device__ globals; no allocation) ---------------
__device__ float g_qkv[(size_t)BT * QKV_LD];     // q|k|v -> sq|..|..
__device__ float g_cwA[(size_t)TT * KBAND];      // band coeffs, tf32-rounded
__device__ float g_uek[(size_t)BB * PADT * 512]; // padded [b][s+128][u|ek] tf32
__device__ float g_nd[(size_t)BT * 512];         // band GEMM out
__device__ float g_Spart[(size_t)BB * 16 * 512];
__device__ float g_S[(size_t)BB * 512];

__device__ float g_xt[(size_t)BT * 256];         // tf32-rounded x
__device__ float g_yt[(size_t)BT * 256];         // tf32-rounded y
__device__ float g_wqkv[(size_t)256 * 768];      // tf32 fused W [k][n]: Wq|Wk|Wv
__device__ float g_wo[(size_t)256 * 256];        // tf32 Wo [k][n]

// ---------------- helpers ---------------------------------------------------
__device__ __forceinline__ float to_tf32(float v) {
    float r;
    asm("cvt.rna.tf32.f32 %0, %1;" : "=f"(r) : "f"(v));
    return r;
}

// ---------------- preps ------------------------------------------------------
__global__ void prep_x(const float* __restrict__ src)
{
    size_t i = ((size_t)blockIdx.x * 256 + threadIdx.x) * 4;
    float4 v = *(const float4*)(src + i);
    v.x = to_tf32(v.x); v.y = to_tf32(v.y);
    v.z = to_tf32(v.z); v.w = to_tf32(v.w);
    *(float4*)&g_xt[i] = v;
}

// blockIdx.x = k (0..255), thread = n (0..767)
__global__ void prep_w(const float* __restrict__ Wq, const float* __restrict__ Wk,
                       const float* __restrict__ Wv, const float* __restrict__ Wo)
{
    int k = blockIdx.x, n = threadIdx.x;
    const float* W = (n < 256) ? Wq : ((n < 512) ? Wk : Wv);
    g_wqkv[(size_t)k * 768 + n] = to_tf32(W[(size_t)k * 256 + (n & 255)]);
    if (n < 256)
        g_wo[(size_t)k * 256 + n] = to_tf32(Wo[(size_t)k * 256 + n]);
}

// ---------------- tf32 GEMM: C[Mx128-tile] = A[m][k] * B[k][n] --------------
#define MMA_TF32(d, a, b) \
    asm volatile("mma.sync.aligned.m16n8k8.row.col.f32.tf32.tf32.f32 " \
                 "{%0,%1,%2,%3},{%4,%5,%6,%7},{%8,%9},{%0,%1,%2,%3};" \
                 : "+f"(d[0]), "+f"(d[1]), "+f"(d[2]), "+f"(d[3]) \
                 : "r"(a[0]), "r"(a[1]), "r"(a[2]), "r"(a[3]), "r"(b[0]), "r"(b[1]))

#define SPA 44    // sA row length (32 k + 12 pad)
#define SPB 136   // sB row length (128 n + 8 pad)

// Generic 128x128 tile tf32 GEMM, 256 threads, warp tile 64x32.
__global__ void __launch_bounds__(256, 2) gemm_tf32(
    const float* __restrict__ A, int lda,
    const float* __restrict__ B, int ldb,
    float* __restrict__ C, int ldc, int K)
{
    __shared__ float sA[128 * SPA];
    __shared__ float sB[32 * SPB];

    const int tid = threadIdx.x;
    const int n0 = blockIdx.x * 128;
    const int m0 = blockIdx.y * 128;

    const int alrow = tid >> 1;
    const int akseg = (tid & 1) * 16;
    const int bkrow = tid >> 3;
    const int bcseg = (tid & 7) * 16;

    const int lane = tid & 31, w = tid >> 5;
    const int wm = w & 1, wn = w >> 1;
    const int quad = lane >> 2, qt = lane & 3;

    float acc[4][4][4];
#pragma unroll
    for (int i = 0; i < 4; i++)
#pragma unroll
        for (int j = 0; j < 4; j++)
#pragma unroll
            for (int e = 0; e < 4; e++) acc[i][j][e] = 0.f;

    for (int k0 = 0; k0 < K; k0 += 32) {
        const float* ap = A + (size_t)(m0 + alrow) * lda + k0 + akseg;
        const float* bp = B + (size_t)(k0 + bkrow) * ldb + n0 + bcseg;
        float* sa = &sA[alrow * SPA + akseg];
        float* sb = &sB[bkrow * SPB + bcseg];
#pragma unroll
        for (int cc = 0; cc < 4; cc++) *(float4*)(sa + cc * 4) = *(const float4*)(ap + cc * 4);
#pragma unroll
        for (int cc = 0; cc < 4; cc++) *(float4*)(sb + cc * 4) = *(const float4*)(bp + cc * 4);
        __syncthreads();

#pragma unroll
        for (int kk = 0; kk < 32; kk += 8) {
            uint32_t afr[4][4], bfr[4][2];
#pragma unroll
            for (int i = 0; i < 4; i++) {
                int m = wm * 64 + i * 16 + quad;
                afr[i][0] = *(const uint32_t*)&sA[m * SPA + kk + qt];
                afr[i][1] = *(const uint32_t*)&sA[(m + 8) * SPA + kk + qt];
                afr[i][2] = *(const uint32_t*)&sA[m * SPA + kk + qt + 4];
                afr[i][3] = *(const uint32_t*)&sA[(m + 8) * SPA + kk + qt + 4];
            }
#pragma unroll
            for (int j = 0; j < 4; j++) {
                int n = wn * 32 + j * 8 + quad;
                bfr[j][0] = *(const uint32_t*)&sB[(kk + qt) * SPB + n];
                bfr[j][1] = *(const uint32_t*)&sB[(kk + qt + 4) * SPB + n];
            }
#pragma unroll
            for (int i = 0; i < 4; i++)
#pragma unroll
                for (int j = 0; j < 4; j++) MMA_TF32(acc[i][j], afr[i], bfr[j]);
        }
        __syncthreads();
    }

#pragma unroll
    for (int i = 0; i < 4; i++) {
#pragma unroll
        for (int j = 0; j < 4; j++) {
            int r = m0 + wm * 64 + i * 16 + quad;
            int cc = n0 + wn * 32 + j * 8 + qt * 2;
            *(float2*)&C[(size_t)r * ldc + cc] = make_float2(acc[i][j][0], acc[i][j][1]);
            *(float2*)&C[(size_t)(r + 8) * ldc + cc] = make_float2(acc[i][j][2], acc[i][j][3]);
        }
    }
}

// ---------------- band coefficient matrix A [2048][384] ---------------------
__global__ void build_cwA(const float* __restrict__ wb)
{
    int t = blockIdx.x;
    int j = threadIdx.x;
    int t0 = (t >> 7) << 7;
    int s = t0 - (WIN - 1) + j;
    float v = 0.f;
    if (s >= 0 && s < TT) {
        int dlt = t - s;
        if (dlt < WIN && dlt > -WIN)
            v = to_tf32(expf(wb[(size_t)t * TT + s]) - 1.f);
    }
    g_cwA[(size_t)t * KBAND + j] = v;
}

__global__ void zero_uek_pad()
{
    size_t i = (size_t)blockIdx.x * 256 + threadIdx.x;
    size_t e = i * 4;
    int b = e / (384 * 512);
    int rem = e % (384 * 512);
    int r = rem / 512;
    int c = rem % 512;
    int p = (r < 128) ? r : (r + 2048);
    *(float4*)&g_uek[((size_t)b * PADT + p) * 512 + c] = make_float4(0.f, 0.f, 0.f, 0.f);
}

// ---------------- elementwise + uek materialization + partial sums ----------
__global__ void ew_reduce()
{
    int b = blockIdx.y;
    int c = blockIdx.x;
    int d = threadIdx.x;
    float se = 0.f, su = 0.f;
    for (int i = 0; i < 128; i++) {
        int t = c * 128 + i;
        size_t base = (size_t)(b * TT + t) * QKV_LD;
        float q = g_qkv[base + d];
        float k = g_qkv[base + 256 + d];
        float v = g_qkv[base + 512 + d];
        float ek = expf(k);
        float u  = ek * v;
        g_qkv[base + d] = 1.f / (1.f + expf(-q));    // sigmoid(q)
        size_t up = ((size_t)b * PADT + t + 128) * 512;
        g_uek[up + d]       = to_tf32(u);
        g_uek[up + 256 + d] = to_tf32(ek);
        se += ek;
        su += u;
    }
    size_t sb = ((size_t)b * 16 + c) * 512;
    g_Spart[sb + d]       = se;
    g_Spart[sb + 256 + d] = su;
}

__global__ void reduce_final()
{
    int b = blockIdx.x;
    int i = threadIdx.x;
    float acc = 0.f;
    for (int c = 0; c < 16; c++)
        acc += g_Spart[((size_t)b * 16 + c) * 512 + i];
    g_S[(size_t)b * 512 + i] = acc;
}

// ---------------- band GEMM: tf32 mma ---------------------------------------
__global__ void __launch_bounds__(256, 2) band_gemm()
{
    __shared__ float sA[128 * SPA];
    __shared__ float sB[32 * SPB];

    const int tid = threadIdx.x;
    const int n0 = blockIdx.x * 128;
    const int t0 = blockIdx.y * 128;
    const int b  = blockIdx.z;

    const float* Ag = g_cwA + (size_t)t0 * KBAND;
    const float* Bg = g_uek + (size_t)b * PADT * 512;

    const int alrow = tid >> 1;
    const int akseg = (tid & 1) * 16;
    const int bkrow = tid >> 3;
    const int bcseg = (tid & 7) * 16;

    const int lane = tid & 31, w = tid >> 5;
    const int wm = w & 1, wn = w >> 1;
    const int quad = lane >> 2, qt = lane & 3;

    float acc[4][4][4];
#pragma unroll
    for (int i = 0; i < 4; i++)
#pragma unroll
        for (int j = 0; j < 4; j++)
#pragma unroll
            for (int e = 0; e < 4; e++) acc[i][j][e] = 0.f;

    for (int k0 = 0; k0 < KBAND; k0 += 32) {
        const float* ap = Ag + (size_t)alrow * KBAND + k0 + akseg;
        const float* bp = Bg + (size_t)(t0 + 1 + k0 + bkrow) * 512 + n0 + bcseg;
        float* sa = &sA[alrow * SPA + akseg];
        float* sb = &sB[bkrow * SPB + bcseg];
#pragma unroll
        for (int cc = 0; cc < 4; cc++) *(float4*)(sa + cc * 4) = *(const float4*)(ap + cc * 4);
#pragma unroll
        for (int cc = 0; cc < 4; cc++) *(float4*)(sb + cc * 4) = *(const float4*)(bp + cc * 4);
        __syncthreads();

#pragma unroll
        for (int kk = 0; kk < 32; kk += 8) {
            uint32_t afr[4][4], bfr[4][2];
#pragma unroll
            for (int i = 0; i < 4; i++) {
                int m = wm * 64 + i * 16 + quad;
                afr[i][0] = *(const uint32_t*)&sA[m * SPA + kk + qt];
                afr[i][1] = *(const uint32_t*)&sA[(m + 8) * SPA + kk + qt];
                afr[i][2] = *(const uint32_t*)&sA[m * SPA + kk + qt + 4];
                afr[i][3] = *(const uint32_t*)&sA[(m + 8) * SPA + kk + qt + 4];
            }
#pragma unroll
            for (int j = 0; j < 4; j++) {
                int n = wn * 32 + j * 8 + quad;
                bfr[j][0] = *(const uint32_t*)&sB[(kk + qt) * SPB + n];
                bfr[j][1] = *(const uint32_t*)&sB[(kk + qt + 4) * SPB + n];
            }
#pragma unroll
            for (int i = 0; i < 4; i++)
#pragma unroll
                for (int j = 0; j < 4; j++) MMA_TF32(acc[i][j], afr[i], bfr[j]);
        }
        __syncthreads();
    }

    float* C = g_nd + (size_t)(b * TT + t0) * 512;
#pragma unroll
    for (int i = 0; i < 4; i++) {
#pragma unroll
        for (int j = 0; j < 4; j++) {
            int r = wm * 64 + i * 16 + quad;
            int cc = n0 + wn * 32 + j * 8 + qt * 2;
            *(float2*)&C[(size_t)r * 512 + cc] = make_float2(acc[i][j][0], acc[i][j][1]);
            *(float2*)&C[(size_t)(r + 8) * 512 + cc] = make_float2(acc[i][j][2], acc[i][j][3]);
        }
    }
}

// ---------------- final gating -> y (tf32) ----------------------------------
__global__ void ybuild()
{
    int r = blockIdx.x;
    int b = r >> 11;
    int d = threadIdx.x;
    float sq  = g_qkv[(size_t)r * QKV_LD + d];
    float num = g_S[(size_t)b * 512 + 256 + d] + g_nd[(size_t)r * 512 + d];
    float den = g_S[(size_t)b * 512 + d]       + g_nd[(size_t)r * 512 + 256 + d];
    g_yt[(size_t)r * 256 + d] = to_tf32(sq * num / den);
}

// ---------------- launch ----------------------------------------------------
extern "C" void kernel_launch(void* const* d_in, const int* in_sizes, int n_in,
                              void* d_out, int out_size)
{
    const float* x      = (const float*)d_in[0];
    const float* Wq     = (const float*)d_in[1];
    const float* Wk     = (const float*)d_in[2];
    const float* Wv     = (const float*)d_in[3];
    const float* Wo     = (const float*)d_in[4];
    const float* w_bias = (const float*)d_in[5];
    float* out = (float*)d_out;

    float *qkv, *xt, *yt, *wqkv, *wo;
    cudaGetSymbolAddress((void**)&qkv, g_qkv);
    cudaGetSymbolAddress((void**)&xt, g_xt);
    cudaGetSymbolAddress((void**)&yt, g_yt);
    cudaGetSymbolAddress((void**)&wqkv, g_wqkv);
    cudaGetSymbolAddress((void**)&wo, g_wo);

    // preps (independent)
    prep_x<<<(BT * 256) / (256 * 4), 256>>>(x);
    prep_w<<<256, 768>>>(Wq, Wk, Wv, Wo);
    build_cwA<<<TT, KBAND>>>(w_bias);
    zero_uek_pad<<<(BB * 384 * 512) / (256 * 4), 256>>>();

    // fused QKV projection: [32768,256] x [256,768] (tf32 single-pass)
    gemm_tf32<<<dim3(768 / 128, BT / 128), 256>>>(xt, 256, wqkv, 768, qkv, QKV_LD, 256);

    // elementwise + uek materialization + global sums
    ew_reduce<<<dim3(16, BB), 256>>>();
    reduce_final<<<BB, 512>>>();

    // banded num/den corrections (tf32)
    band_gemm<<<dim3(4, 16, BB), 256>>>();

    // gating, then output projection: [32768,256] x [256,256]
    ybuild<<<BT, 256>>>();
    gemm_tf32<<<dim3(256 / 128, BT / 128), 256>>>(yt, 256, wo, 256, out, DD, 256);
}

// round 11
// speedup vs baseline: 1.2239x; 1.2239x over previous
#include <cuda_runtime.h>
#include <cuda_bf16.h>
#include <cstddef>
#include <cstdint>

// Problem constants (B=16, T=2048, D=256, WINDOW=128)
#define BB 16
#define TT 2048
#define DD 256
#define WIN 128
#define BT (BB*TT)          // 32768
#define QKV_LD 768
#define PADT 2432
#define KBAND 384

// ---------------- scratch (__device__ globals; no allocation) ---------------
__device__ float g_qkv[(size_t)BT * QKV_LD];     // q|k|v -> sq|..|..
__device__ float g_cwA[(size_t)TT * KBAND];
__device__ float g_uek[(size_t)BB * PADT * 512];
__device__ float g_nd[(size_t)BT * 512];
__device__ float g_Spart[(size_t)BB * 16 * 512];
__device__ float g_S[(size_t)BB * 512];

__device__ float g_xp[(size_t)BT * 256];         // x, packed fragment order
__device__ float g_yp[(size_t)BT * 256];         // y, packed fragment order
__device__ float g_ytmp[(size_t)BT * 256];       // y, row-major temp
__device__ float g_wqkv[(size_t)256 * 768];      // fused W, packed (6 nblk x 8 kc)
__device__ float g_wo[(size_t)256 * 256];        // Wo, packed (2 nblk x 8 kc)

// ---------------- helpers ---------------------------------------------------
__device__ __forceinline__ float to_tf32(float v) {
    float r;
    asm("cvt.rna.tf32.f32 %0, %1;" : "=f"(r) : "f"(v));
    return r;
}
__device__ __forceinline__ uint32_t smem_u32(const void* p) {
    return (uint32_t)__cvta_generic_to_shared(p);
}
#define CP16(dst, src) \
    asm volatile("cp.async.cg.shared.global [%0], [%1], 16;" :: "r"(dst), "l"(src))

// ---------------- operand packing -------------------------------------------
// A packed: region(mblk 0..M/128-1, kc 0..7) = 4096 floats:
//   [(kk*8+mi)*32 + lane] * 4 floats = the m16n8k8 A fragment
//   {A[r][c], A[r+8][c], A[r][c+4], A[r+8][c+4]},
//   r = mblk*128+mi*16+quad, c = kc*32+kk*8+qt, quad=lane>>2, qt=lane&3.
__global__ void pack_a(const float* __restrict__ src, float* __restrict__ dst)
{
    int fid = blockIdx.x * 256 + threadIdx.x;     // float4 id
    int rg = fid >> 10;
    int q  = fid & 1023;
    int slot = q >> 5;
    int lane = q & 31;
    int mblk = rg >> 3, kc = rg & 7;
    int kk = slot >> 3, mi = slot & 7;
    int quad = lane >> 2, qt = lane & 3;
    int r0 = mblk * 128 + mi * 16 + quad;
    int c0 = kc * 32 + kk * 8 + qt;
    const float* s = src + (size_t)r0 * 256 + c0;
    float4 v;
    v.x = to_tf32(s[0]);
    v.y = to_tf32(s[8 * 256]);
    v.z = to_tf32(s[4]);
    v.w = to_tf32(s[8 * 256 + 4]);
    *(float4*)&dst[(size_t)fid * 4] = v;
}

// B packed: region(nblk, kc) = 4096 floats:
//   [(kk*16+nj)*32 + lane] * 2 floats = {W[k0][n], W[k0+4][n]},
//   k0 = kc*32+kk*8+qt, n = nblk*128+nj*8+quad.
__global__ void pack_w(const float* __restrict__ Wq, const float* __restrict__ Wk,
                       const float* __restrict__ Wv, const float* __restrict__ Wo)
{
    int f2 = blockIdx.x * 256 + threadIdx.x;      // float2 id; 98304 qkv + 32768 wo
    bool isO = f2 >= 98304;
    int base = isO ? (f2 - 98304) : f2;
    int rg = base >> 11;
    int q  = base & 2047;
    int slot = q >> 5;
    int lane = q & 31;
    int nblk = rg >> 3, kc = rg & 7;
    int kk = slot >> 4, nj = slot & 15;
    int quad = lane >> 2, qt = lane & 3;
    int k0 = kc * 32 + kk * 8 + qt;
    int n = nblk * 128 + nj * 8 + quad;
    float v0, v1;
    if (isO) {
        v0 = Wo[(size_t)k0 * 256 + n];
        v1 = Wo[(size_t)(k0 + 4) * 256 + n];
    } else {
        const float* W = (n < 256) ? Wq : ((n < 512) ? Wk : Wv);
        int nn = n & 255;
        v0 = W[(size_t)k0 * 256 + nn];
        v1 = W[(size_t)(k0 + 4) * 256 + nn];
    }
    float* dst = isO ? g_wo : g_wqkv;
    *(float2*)&dst[(size_t)base * 2] = make_float2(to_tf32(v0), to_tf32(v1));
}

// ---------------- packed tf32 GEMM ------------------------------------------
#define MMA_TF32V(d, a, b) \
    asm volatile("mma.sync.aligned.m16n8k8.row.col.f32.tf32.tf32.f32 " \
                 "{%0,%1,%2,%3},{%4,%5,%6,%7},{%8,%9},{%0,%1,%2,%3};" \
                 : "+f"(d[0]), "+f"(d[1]), "+f"(d[2]), "+f"(d[3]) \
                 : "r"(a.x), "r"(a.y), "r"(a.z), "r"(a.w), "r"(b.x), "r"(b.y))

#define MMA_TF32(d, a, b) \
    asm volatile("mma.sync.aligned.m16n8k8.row.col.f32.tf32.tf32.f32 " \
                 "{%0,%1,%2,%3},{%4,%5,%6,%7},{%8,%9},{%0,%1,%2,%3};" \
                 : "+f"(d[0]), "+f"(d[1]), "+f"(d[2]), "+f"(d[3]) \
                 : "r"(a[0]), "r"(a[1]), "r"(a[2]), "r"(a[3]), "r"(b[0]), "r"(b[1]))

#define PG_SMEM (2 * 8192 * 4)   // 2 stages x (4096 A + 4096 B) floats

// C[128x128 tile] = A_packed x B_packed. 256 threads, warp tile 64x32.
__global__ void __launch_bounds__(256, 2) gemm_tf32p(
    const float* __restrict__ Ap, const float* __restrict__ Bp,
    float* __restrict__ C, int ldc)
{
    extern __shared__ float sm[];
    const int tid = threadIdx.x;
    const int nblk = blockIdx.x;
    const int mblk = blockIdx.y;

    const float* Abase = Ap + (size_t)mblk * 8 * 4096;
    const float* Bbase = Bp + (size_t)nblk * 8 * 4096;

    const int lane = tid & 31, w = tid >> 5;
    const int wm = w & 1, wn = w >> 1;
    const int quad = lane >> 2, qt = lane & 3;

    float acc[4][4][4];
#pragma unroll
    for (int i = 0; i < 4; i++)
#pragma unroll
        for (int j = 0; j < 4; j++)
#pragma unroll
            for (int e = 0; e < 4; e++) acc[i][j][e] = 0.f;

    // preload chunk 0 -> stage 0
    {
        float* dA = sm; float* dB = sm + 4096;
#pragma unroll
        for (int r = 0; r < 4; r++) {
            CP16(smem_u32(dA + (r * 256 + tid) * 4), Abase + (size_t)(r * 256 + tid) * 4);
            CP16(smem_u32(dB + (r * 256 + tid) * 4), Bbase + (size_t)(r * 256 + tid) * 4);
        }
        asm volatile("cp.async.commit_group;");
    }

    int stage = 0;
    for (int c = 0; c < 8; c++) {
        if (c < 7) {
            float* dA = sm + (stage ^ 1) * 8192;
            float* dB = dA + 4096;
            const float* gA = Abase + (size_t)(c + 1) * 4096;
            const float* gB = Bbase + (size_t)(c + 1) * 4096;
#pragma unroll
            for (int r = 0; r < 4; r++) {
                CP16(smem_u32(dA + (r * 256 + tid) * 4), gA + (size_t)(r * 256 + tid) * 4);
                CP16(smem_u32(dB + (r * 256 + tid) * 4), gB + (size_t)(r * 256 + tid) * 4);
            }
            asm volatile("cp.async.commit_group;");
            asm volatile("cp.async.wait_group 1;");
        } else {
            asm volatile("cp.async.wait_group 0;");
        }
        __syncthreads();

        const float* A = sm + stage * 8192;
        const float* B = A + 4096;
#pragma unroll
        for (int kk = 0; kk < 4; kk++) {
            uint4 af[4];
            uint2 bf[4];
#pragma unroll
            for (int i = 0; i < 4; i++)
                af[i] = *(const uint4*)&A[(kk * 8 + wm * 4 + i) * 128 + lane * 4];
#pragma unroll
            for (int j = 0; j < 4; j++)
                bf[j] = *(const uint2*)&B[(kk * 16 + wn * 4 + j) * 64 + lane * 2];
#pragma unroll
            for (int i = 0; i < 4; i++)
#pragma unroll
                for (int j = 0; j < 4; j++) MMA_TF32V(acc[i][j], af[i], bf[j]);
        }
        __syncthreads();
        stage ^= 1;
    }

#pragma unroll
    for (int i = 0; i < 4; i++) {
#pragma unroll
        for (int j = 0; j < 4; j++) {
            int r = mblk * 128 + wm * 64 + i * 16 + quad;
            int cc = nblk * 128 + wn * 32 + j * 8 + qt * 2;
            *(float2*)&C[(size_t)r * ldc + cc] = make_float2(acc[i][j][0], acc[i][j][1]);
            *(float2*)&C[(size_t)(r + 8) * ldc + cc] = make_float2(acc[i][j][2], acc[i][j][3]);
        }
    }
}

// ---------------- band coefficient matrix A [2048][384] ---------------------
__global__ void build_cwA(const float* __restrict__ wb)
{
    int t = blockIdx.x;
    int j = threadIdx.x;
    int t0 = (t >> 7) << 7;
    int s = t0 - (WIN - 1) + j;
    float v = 0.f;
    if (s >= 0 && s < TT) {
        int dlt = t - s;
        if (dlt < WIN && dlt > -WIN)
            v = to_tf32(expf(wb[(size_t)t * TT + s]) - 1.f);
    }
    g_cwA[(size_t)t * KBAND + j] = v;
}

__global__ void zero_uek_pad()
{
    size_t i = (size_t)blockIdx.x * 256 + threadIdx.x;
    size_t e = i * 4;
    int b = e / (384 * 512);
    int rem = e % (384 * 512);
    int r = rem / 512;
    int c = rem % 512;
    int p = (r < 128) ? r : (r + 2048);
    *(float4*)&g_uek[((size_t)b * PADT + p) * 512 + c] = make_float4(0.f, 0.f, 0.f, 0.f);
}

// ---------------- elementwise + uek materialization + partial sums ----------
__global__ void ew_reduce()
{
    int b = blockIdx.y;
    int c = blockIdx.x;
    int d = threadIdx.x;
    float se = 0.f, su = 0.f;
    for (int i = 0; i < 128; i++) {
        int t = c * 128 + i;
        size_t base = (size_t)(b * TT + t) * QKV_LD;
        float q = g_qkv[base + d];
        float k = g_qkv[base + 256 + d];
        float v = g_qkv[base + 512 + d];
        float ek = expf(k);
        float u  = ek * v;
        g_qkv[base + d] = 1.f / (1.f + expf(-q));    // sigmoid(q)
        size_t up = ((size_t)b * PADT + t + 128) * 512;
        g_uek[up + d]       = to_tf32(u);
        g_uek[up + 256 + d] = to_tf32(ek);
        se += ek;
        su += u;
    }
    size_t sb = ((size_t)b * 16 + c) * 512;
    g_Spart[sb + d]       = se;
    g_Spart[sb + 256 + d] = su;
}

__global__ void reduce_final()
{
    int b = blockIdx.x;
    int i = threadIdx.x;
    float acc = 0.f;
    for (int c = 0; c < 16; c++)
        acc += g_Spart[((size_t)b * 16 + c) * 512 + i];
    g_S[(size_t)b * 512 + i] = acc;
}

// ---------------- band GEMM: tf32 mma (unchanged) ---------------------------
#define SPA 44
#define SPB 136

__global__ void __launch_bounds__(256, 2) band_gemm()
{
    __shared__ float sA[128 * SPA];
    __shared__ float sB[32 * SPB];

    const int tid = threadIdx.x;
    const int n0 = blockIdx.x * 128;
    const int t0 = blockIdx.y * 128;
    const int b  = blockIdx.z;

    const float* Ag = g_cwA + (size_t)t0 * KBAND;
    const float* Bg = g_uek + (size_t)b * PADT * 512;

    const int alrow = tid >> 1;
    const int akseg = (tid & 1) * 16;
    const int bkrow = tid >> 3;
    const int bcseg = (tid & 7) * 16;

    const int lane = tid & 31, w = tid >> 5;
    const int wm = w & 1, wn = w >> 1;
    const int quad = lane >> 2, qt = lane & 3;

    float acc[4][4][4];
#pragma unroll
    for (int i = 0; i < 4; i++)
#pragma unroll
        for (int j = 0; j < 4; j++)
#pragma unroll
            for (int e = 0; e < 4; e++) acc[i][j][e] = 0.f;

    for (int k0 = 0; k0 < KBAND; k0 += 32) {
        const float* ap = Ag + (size_t)alrow * KBAND + k0 + akseg;
        const float* bp = Bg + (size_t)(t0 + 1 + k0 + bkrow) * 512 + n0 + bcseg;
        float* sa = &sA[alrow * SPA + akseg];
        float* sb = &sB[bkrow * SPB + bcseg];
#pragma unroll
        for (int cc = 0; cc < 4; cc++) *(float4*)(sa + cc * 4) = *(const float4*)(ap + cc * 4);
#pragma unroll
        for (int cc = 0; cc < 4; cc++) *(float4*)(sb + cc * 4) = *(const float4*)(bp + cc * 4);
        __syncthreads();

#pragma unroll
        for (int kk = 0; kk < 32; kk += 8) {
            uint32_t afr[4][4], bfr[4][2];
#pragma unroll
            for (int i = 0; i < 4; i++) {
                int m = wm * 64 + i * 16 + quad;
                afr[i][0] = *(const uint32_t*)&sA[m * SPA + kk + qt];
                afr[i][1] = *(const uint32_t*)&sA[(m + 8) * SPA + kk + qt];
                afr[i][2] = *(const uint32_t*)&sA[m * SPA + kk + qt + 4];
                afr[i][3] = *(const uint32_t*)&sA[(m + 8) * SPA + kk + qt + 4];
            }
#pragma unroll
            for (int j = 0; j < 4; j++) {
                int n = wn * 32 + j * 8 + quad;
                bfr[j][0] = *(const uint32_t*)&sB[(kk + qt) * SPB + n];
                bfr[j][1] = *(const uint32_t*)&sB[(kk + qt + 4) * SPB + n];
            }
#pragma unroll
            for (int i = 0; i < 4; i++)
#pragma unroll
                for (int j = 0; j < 4; j++) MMA_TF32(acc[i][j], afr[i], bfr[j]);
        }
        __syncthreads();
    }

    float* C = g_nd + (size_t)(b * TT + t0) * 512;
#pragma unroll
    for (int i = 0; i < 4; i++) {
#pragma unroll
        for (int j = 0; j < 4; j++) {
            int r = wm * 64 + i * 16 + quad;
            int cc = n0 + wn * 32 + j * 8 + qt * 2;
            *(float2*)&C[(size_t)r * 512 + cc] = make_float2(acc[i][j][0], acc[i][j][1]);
            *(float2*)&C[(size_t)(r + 8) * 512 + cc] = make_float2(acc[i][j][2], acc[i][j][3]);
        }
    }
}

// ---------------- final gating -> y (row-major temp) ------------------------
__global__ void ybuild()
{
    int r = blockIdx.x;
    int b = r >> 11;
    int d = threadIdx.x;
    float sq  = g_qkv[(size_t)r * QKV_LD + d];
    float num = g_S[(size_t)b * 512 + 256 + d] + g_nd[(size_t)r * 512 + d];
    float den = g_S[(size_t)b * 512 + d]       + g_nd[(size_t)r * 512 + 256 + d];
    g_ytmp[(size_t)r * 256 + d] = sq * num / den;
}

// ---------------- launch ----------------------------------------------------
extern "C" void kernel_launch(void* const* d_in, const int* in_sizes, int n_in,
                              void* d_out, int out_size)
{
    const float* x      = (const float*)d_in[0];
    const float* Wq     = (const float*)d_in[1];
    const float* Wk     = (const float*)d_in[2];
    const float* Wv     = (const float*)d_in[3];
    const float* Wo     = (const float*)d_in[4];
    const float* w_bias = (const float*)d_in[5];
    float* out = (float*)d_out;

    float *qkv, *xp, *yp, *ytmp, *wqkv, *wo;
    cudaGetSymbolAddress((void**)&qkv, g_qkv);
    cudaGetSymbolAddress((void**)&xp, g_xp);
    cudaGetSymbolAddress((void**)&yp, g_yp);
    cudaGetSymbolAddress((void**)&ytmp, g_ytmp);
    cudaGetSymbolAddress((void**)&wqkv, g_wqkv);
    cudaGetSymbolAddress((void**)&wo, g_wo);

    cudaFuncSetAttribute(gemm_tf32p,
                         cudaFuncAttributeMaxDynamicSharedMemorySize, PG_SMEM);

    // preps (independent)
    pack_a<<<(BT * 64) / 256, 256>>>(x, xp);
    pack_w<<<(98304 + 32768) / 256, 256>>>(Wq, Wk, Wv, Wo);
    build_cwA<<<TT, KBAND>>>(w_bias);
    zero_uek_pad<<<(BB * 384 * 512) / (256 * 4), 256>>>();

    // fused QKV projection: [32768,256] x [256,768] (packed tf32)
    gemm_tf32p<<<dim3(6, BT / 128), 256, PG_SMEM>>>(xp, wqkv, qkv, QKV_LD);

    // elementwise + uek materialization + global sums
    ew_reduce<<<dim3(16, BB), 256>>>();
    reduce_final<<<BB, 512>>>();

    // banded num/den corrections (tf32)
    band_gemm<<<dim3(4, 16, BB), 256>>>();

    // gating -> pack -> output projection: [32768,256] x [256,256]
    ybuild<<<BT, 256>>>();
    pack_a<<<(BT * 64) / 256, 256>>>(ytmp, yp);
    gemm_tf32p<<<dim3(2, BT / 128), 256, PG_SMEM>>>(yp, wo, out, DD);
}

// round 13
// speedup vs baseline: 1.4203x; 1.1604x over previous
#include <cuda_runtime.h>
#include <cuda_bf16.h>
#include <cstddef>
#include <cstdint>

// Problem constants (B=16, T=2048, D=256, WINDOW=128)
#define BB 16
#define TT 2048
#define DD 256
#define WIN 128
#define BT (BB*TT)          // 32768
#define QKV_LD 768
#define PADT 2432
#define KBAND 384

// ---------------- scratch (__device__ globals; no allocation) ---------------
__device__ float g_qkv[(size_t)BT * QKV_LD];     // q|k|v -> sq|..|..
__device__ float g_cwP[(size_t)16 * 12 * 4096];  // band A, packed fragment order
__device__ float g_uek[(size_t)BB * PADT * 512]; // padded [b][s+128][u|ek] tf32
__device__ float g_nd[(size_t)BT * 512];
__device__ float g_Spart[(size_t)BB * 16 * 512];
__device__ float g_S[(size_t)BB * 512];

__device__ float g_xp[(size_t)BT * 256];         // x, packed fragment order
__device__ float g_yp[(size_t)BT * 256];         // y, packed fragment order
__device__ float g_wqkv[(size_t)256 * 768];      // fused W packed (6 nblk x 8 kc)
__device__ float g_wo[(size_t)256 * 256];        // Wo packed (2 nblk x 8 kc)

// ---------------- helpers ---------------------------------------------------
__device__ __forceinline__ float to_tf32(float v) {
    float r;
    asm("cvt.rna.tf32.f32 %0, %1;" : "=f"(r) : "f"(v));
    return r;
}
__device__ __forceinline__ uint32_t smem_u32(const void* p) {
    return (uint32_t)__cvta_generic_to_shared(p);
}
#define CP16(dst, src) \
    asm volatile("cp.async.cg.shared.global [%0], [%1], 16;" :: "r"(dst), "l"(src))

// ---------------- operand packing -------------------------------------------
// A packed: region(mblk, kc) = 4096 floats; [(kk*8+mi)*32+lane]*4 =
// {A[r][c], A[r+8][c], A[r][c+4], A[r+8][c+4]},
// r = mblk*128+mi*16+quad, c = kc*32+kk*8+qt.
__global__ void pack_a(const float* __restrict__ src, float* __restrict__ dst)
{
    int fid = blockIdx.x * 256 + threadIdx.x;
    int rg = fid >> 10;
    int q  = fid & 1023;
    int slot = q >> 5;
    int lane = q & 31;
    int mblk = rg >> 3, kc = rg & 7;
    int kk = slot >> 3, mi = slot & 7;
    int quad = lane >> 2, qt = lane & 3;
    int r0 = mblk * 128 + mi * 16 + quad;
    int c0 = kc * 32 + kk * 8 + qt;
    const float* s = src + (size_t)r0 * 256 + c0;
    float4 v;
    v.x = to_tf32(s[0]);
    v.y = to_tf32(s[8 * 256]);
    v.z = to_tf32(s[4]);
    v.w = to_tf32(s[8 * 256 + 4]);
    *(float4*)&dst[(size_t)fid * 4] = v;
}

__global__ void pack_w(const float* __restrict__ Wq, const float* __restrict__ Wk,
                       const float* __restrict__ Wv, const float* __restrict__ Wo)
{
    int f2 = blockIdx.x * 256 + threadIdx.x;
    bool isO = f2 >= 98304;
    int base = isO ? (f2 - 98304) : f2;
    int rg = base >> 11;
    int q  = base & 2047;
    int slot = q >> 5;
    int lane = q & 31;
    int nblk = rg >> 3, kc = rg & 7;
    int kk = slot >> 4, nj = slot & 15;
    int quad = lane >> 2, qt = lane & 3;
    int k0 = kc * 32 + kk * 8 + qt;
    int n = nblk * 128 + nj * 8 + quad;
    float v0, v1;
    if (isO) {
        v0 = Wo[(size_t)k0 * 256 + n];
        v1 = Wo[(size_t)(k0 + 4) * 256 + n];
    } else {
        const float* W = (n < 256) ? Wq : ((n < 512) ? Wk : Wv);
        int nn = n & 255;
        v0 = W[(size_t)k0 * 256 + nn];
        v1 = W[(size_t)(k0 + 4) * 256 + nn];
    }
    float* dst = isO ? g_wo : g_wqkv;
    *(float2*)&dst[(size_t)base * 2] = make_float2(to_tf32(v0), to_tf32(v1));
}

// ---------------- packed tf32 GEMM ------------------------------------------
#define MMA_TF32V(d, a, b) \
    asm volatile("mma.sync.aligned.m16n8k8.row.col.f32.tf32.tf32.f32 " \
                 "{%0,%1,%2,%3},{%4,%5,%6,%7},{%8,%9},{%0,%1,%2,%3};" \
                 : "+f"(d[0]), "+f"(d[1]), "+f"(d[2]), "+f"(d[3]) \
                 : "r"(a.x), "r"(a.y), "r"(a.z), "r"(a.w), "r"(b.x), "r"(b.y))

#define MMA_TF32S(d, a, b0, b1) \
    asm volatile("mma.sync.aligned.m16n8k8.row.col.f32.tf32.tf32.f32 " \
                 "{%0,%1,%2,%3},{%4,%5,%6,%7},{%8,%9},{%0,%1,%2,%3};" \
                 : "+f"(d[0]), "+f"(d[1]), "+f"(d[2]), "+f"(d[3]) \
                 : "r"(a.x), "r"(a.y), "r"(a.z), "r"(a.w), "r"(b0), "r"(b1))

#define PG_SMEM (2 * 8192 * 4)

__global__ void __launch_bounds__(256, 2) gemm_tf32p(
    const float* __restrict__ Ap, const float* __restrict__ Bp,
    float* __restrict__ C, int ldc)
{
    extern __shared__ float sm[];
    const int tid = threadIdx.x;
    const int nblk = blockIdx.x;
    const int mblk = blockIdx.y;

    const float* Abase = Ap + (size_t)mblk * 8 * 4096;
    const float* Bbase = Bp + (size_t)nblk * 8 * 4096;

    const int lane = tid & 31, w = tid >> 5;
    const int wm = w & 1, wn = w >> 1;
    const int quad = lane >> 2, qt = lane & 3;

    float acc[4][4][4];
#pragma unroll
    for (int i = 0; i < 4; i++)
#pragma unroll
        for (int j = 0; j < 4; j++)
#pragma unroll
            for (int e = 0; e < 4; e++) acc[i][j][e] = 0.f;

    {
        float* dA = sm; float* dB = sm + 4096;
#pragma unroll
        for (int r = 0; r < 4; r++) {
            CP16(smem_u32(dA + (r * 256 + tid) * 4), Abase + (size_t)(r * 256 + tid) * 4);
            CP16(smem_u32(dB + (r * 256 + tid) * 4), Bbase + (size_t)(r * 256 + tid) * 4);
        }
        asm volatile("cp.async.commit_group;");
    }

    int stage = 0;
    for (int c = 0; c < 8; c++) {
        if (c < 7) {
            float* dA = sm + (stage ^ 1) * 8192;
            float* dB = dA + 4096;
            const float* gA = Abase + (size_t)(c + 1) * 4096;
            const float* gB = Bbase + (size_t)(c + 1) * 4096;
#pragma unroll
            for (int r = 0; r < 4; r++) {
                CP16(smem_u32(dA + (r * 256 + tid) * 4), gA + (size_t)(r * 256 + tid) * 4);
                CP16(smem_u32(dB + (r * 256 + tid) * 4), gB + (size_t)(r * 256 + tid) * 4);
            }
            asm volatile("cp.async.commit_group;");
            asm volatile("cp.async.wait_group 1;");
        } else {
            asm volatile("cp.async.wait_group 0;");
        }
        __syncthreads();

        const float* A = sm + stage * 8192;
        const float* B = A + 4096;
#pragma unroll
        for (int kk = 0; kk < 4; kk++) {
            uint4 af[4];
            uint2 bf[4];
#pragma unroll
            for (int i = 0; i < 4; i++)
                af[i] = *(const uint4*)&A[(kk * 8 + wm * 4 + i) * 128 + lane * 4];
#pragma unroll
            for (int j = 0; j < 4; j++)
                bf[j] = *(const uint2*)&B[(kk * 16 + wn * 4 + j) * 64 + lane * 2];
#pragma unroll
            for (int i = 0; i < 4; i++)
#pragma unroll
                for (int j = 0; j < 4; j++) MMA_TF32V(acc[i][j], af[i], bf[j]);
        }
        __syncthreads();
        stage ^= 1;
    }

#pragma unroll
    for (int i = 0; i < 4; i++) {
#pragma unroll
        for (int j = 0; j < 4; j++) {
            int r = mblk * 128 + wm * 64 + i * 16 + quad;
            int cc = nblk * 128 + wn * 32 + j * 8 + qt * 2;
            *(float2*)&C[(size_t)r * ldc + cc] = make_float2(acc[i][j][0], acc[i][j][1]);
            *(float2*)&C[(size_t)(r + 8) * ldc + cc] = make_float2(acc[i][j][2], acc[i][j][3]);
        }
    }
}

// ---------------- band A, packed fragment order -----------------------------
// Convention: for t-tile t0, j=0..383 maps to s = t0 - 128 + j.
__device__ __forceinline__ float cw_val(const float* wb, int t, int t0, int j)
{
    int s = t0 - 128 + j;
    int dlt = t - s;
    if (s < 0 || s >= TT || dlt >= WIN || dlt <= -WIN) return 0.f;
    return to_tf32(expf(wb[(size_t)t * TT + s]) - 1.f);
}

// region(tile, kc 0..11) = 4096 floats, same layout as pack_a regions
__global__ void build_cwP(const float* __restrict__ wb)
{
    int fid = blockIdx.x * 256 + threadIdx.x;   // float4 id; 196608 total
    int rg = fid >> 10;          // tile*12 + kc
    int q  = fid & 1023;
    int slot = q >> 5;           // 0..31
    int lane = q & 31;
    int tile = rg / 12, kc = rg - tile * 12;
    int kk = slot >> 3, mi = slot & 7;
    int quad = lane >> 2, qt = lane & 3;
    int t0 = tile * 128;
    int t = t0 + mi * 16 + quad;
    int j = kc * 32 + kk * 8 + qt;
    float4 v;
    v.x = cw_val(wb, t,     t0, j);
    v.y = cw_val(wb, t + 8, t0, j);
    v.z = cw_val(wb, t,     t0, j + 4);
    v.w = cw_val(wb, t + 8, t0, j + 4);
    *(float4*)&g_cwP[(size_t)fid * 4] = v;
}

__global__ void zero_uek_pad()
{
    size_t i = (size_t)blockIdx.x * 256 + threadIdx.x;
    size_t e = i * 4;
    int b = e / (384 * 512);
    int rem = e % (384 * 512);
    int r = rem / 512;
    int c = rem % 512;
    int p = (r < 128) ? r : (r + 2048);
    *(float4*)&g_uek[((size_t)b * PADT + p) * 512 + c] = make_float4(0.f, 0.f, 0.f, 0.f);
}

// ---------------- elementwise + uek materialization + partial sums ----------
__global__ void ew_reduce()
{
    int b = blockIdx.y;
    int c = blockIdx.x;
    int d = threadIdx.x;
    float se = 0.f, su = 0.f;
    for (int i = 0; i < 128; i++) {
        int t = c * 128 + i;
        size_t base = (size_t)(b * TT + t) * QKV_LD;
        float q = g_qkv[base + d];
        float k = g_qkv[base + 256 + d];
        float v = g_qkv[base + 512 + d];
        float ek = expf(k);
        float u  = ek * v;
        g_qkv[base + d] = 1.f / (1.f + expf(-q));    // sigmoid(q)
        size_t up = ((size_t)b * PADT + t + 128) * 512;
        g_uek[up + d]       = to_tf32(u);
        g_uek[up + 256 + d] = to_tf32(ek);
        se += ek;
        su += u;
    }
    size_t sb = ((size_t)b * 16 + c) * 512;
    g_Spart[sb + d]       = se;
    g_Spart[sb + 256 + d] = su;
}

__global__ void reduce_final()
{
    int b = blockIdx.x;
    int i = threadIdx.x;
    float acc = 0.f;
    for (int c = 0; c < 16; c++)
        acc += g_Spart[((size_t)b * 16 + c) * 512 + i];
    g_S[(size_t)b * 512 + i] = acc;
}

// ---------------- band GEMM: packed A + cp.async + triangle skip ------------
#define SPB 136
#define BSM_A 4096                   // 128 t x 32 j floats
#define BSM_B (32 * SPB)             // 4352 floats
#define BSTG (BSM_A + BSM_B)         // 8448 floats per stage
#define BAND_SMEM (2 * BSTG * 4)     // 67584 bytes

__global__ void __launch_bounds__(256, 2) band_gemm_p()
{
    extern __shared__ float bsm[];
    const int tid = threadIdx.x;
    const int nblk = blockIdx.x;     // 0..3
    const int tile = blockIdx.y;     // 0..15
    const int b    = blockIdx.z;
    const int t0 = tile * 128;
    const int n0 = nblk * 128;

    const float* Ap = g_cwP + (size_t)tile * 12 * 4096;
    const float* Bg = g_uek + (size_t)b * PADT * 512;

    const int lane = tid & 31, w = tid >> 5;
    const int wm = w & 1, wn = w >> 1;
    const int quad = lane >> 2, qt = lane & 3;
    const int brow = tid >> 3;
    const int bcol = (tid & 7) * 16;

    float acc[4][4][4];
#pragma unroll
    for (int i = 0; i < 4; i++)
#pragma unroll
        for (int j = 0; j < 4; j++)
#pragma unroll
            for (int e = 0; e < 4; e++) acc[i][j][e] = 0.f;

    // stage loader: A 16KB linear, B 32 rows x 128 floats into pad-136 smem
    auto issue = [&](int stg, int c) {
        float* sA = bsm + stg * BSTG;
        float* sB = sA + BSM_A;
        const float* gA = Ap + (size_t)c * 4096;
#pragma unroll
        for (int r = 0; r < 4; r++)
            CP16(smem_u32(sA + (r * 256 + tid) * 4), gA + (size_t)(r * 256 + tid) * 4);
        const float* bp = Bg + (size_t)(t0 + c * 32 + brow) * 512 + n0 + bcol;
        float* dst = sB + brow * SPB + bcol;
#pragma unroll
        for (int s = 0; s < 4; s++)
            CP16(smem_u32(dst + s * 4), bp + s * 4);
        asm volatile("cp.async.commit_group;");
    };

    issue(0, 0);
    int stage = 0;
    for (int c = 0; c < 12; c++) {
        if (c < 11) {
            issue(stage ^ 1, c + 1);
            asm volatile("cp.async.wait_group 1;");
        } else {
            asm volatile("cp.async.wait_group 0;");
        }
        __syncthreads();

        const float* A = bsm + stage * BSTG;
        const float* B = A + BSM_A;
        const int tbw = wm * 64;
#pragma unroll
        for (int kk = 0; kk < 4; kk++) {
            int jb = c * 32 + kk * 8;
            if (jb >= tbw - 6 && jb <= tbw + 318) {
                uint32_t b0[4], b1[4];
#pragma unroll
                for (int j = 0; j < 4; j++) {
                    int n = wn * 32 + j * 8 + quad;
                    b0[j] = *(const uint32_t*)&B[(kk * 8 + qt) * SPB + n];
                    b1[j] = *(const uint32_t*)&B[(kk * 8 + qt + 4) * SPB + n];
                }
#pragma unroll
                for (int i = 0; i < 4; i++) {
                    int tb = tbw + i * 16;
                    if (jb >= tb - 6 && jb <= tb + 270) {
                        uint4 af = *(const uint4*)&A[(kk * 8 + wm * 4 + i) * 128 + lane * 4];
#pragma unroll
                        for (int j = 0; j < 4; j++)
                            MMA_TF32S(acc[i][j], af, b0[j], b1[j]);
                    }
                }
            }
        }
        __syncthreads();
        stage ^= 1;
    }

    float* C = g_nd + (size_t)(b * TT + t0) * 512;
#pragma unroll
    for (int i = 0; i < 4; i++) {
#pragma unroll
        for (int j = 0; j < 4; j++) {
            int r = wm * 64 + i * 16 + quad;
            int cc = n0 + wn * 32 + j * 8 + qt * 2;
            *(float2*)&C[(size_t)r * 512 + cc] = make_float2(acc[i][j][0], acc[i][j][1]);
            *(float2*)&C[(size_t)(r + 8) * 512 + cc] = make_float2(acc[i][j][2], acc[i][j][3]);
        }
    }
}

// ---------------- fused gating + fragment pack of y -------------------------
__device__ __forceinline__ float y_val(int r, int c)
{
    int b = r >> 11;
    float sq  = g_qkv[(size_t)r * QKV_LD + c];
    float num = g_S[(size_t)b * 512 + 256 + c] + g_nd[(size_t)r * 512 + c];
    float den = g_S[(size_t)b * 512 + c]       + g_nd[(size_t)r * 512 + 256 + c];
    return to_tf32(sq * num / den);
}

__global__ void pack_y()
{
    int fid = blockIdx.x * 256 + threadIdx.x;
    int rg = fid >> 10;
    int q  = fid & 1023;
    int slot = q >> 5;
    int lane = q & 31;
    int mblk = rg >> 3, kc = rg & 7;
    int kk = slot >> 3, mi = slot & 7;
    int quad = lane >> 2, qt = lane & 3;
    int r0 = mblk * 128 + mi * 16 + quad;
    int c0 = kc * 32 + kk * 8 + qt;
    float4 v;
    v.x = y_val(r0,     c0);
    v.y = y_val(r0 + 8, c0);
    v.z = y_val(r0,     c0 + 4);
    v.w = y_val(r0 + 8, c0 + 4);
    *(float4*)&g_yp[(size_t)fid * 4] = v;
}

// ---------------- launch ----------------------------------------------------
extern "C" void kernel_launch(void* const* d_in, const int* in_sizes, int n_in,
                              void* d_out, int out_size)
{
    const float* x      = (const float*)d_in[0];
    const float* Wq     = (const float*)d_in[1];
    const float* Wk     = (const float*)d_in[2];
    const float* Wv     = (const float*)d_in[3];
    const float* Wo     = (const float*)d_in[4];
    const float* w_bias = (const float*)d_in[5];
    float* out = (float*)d_out;

    float *qkv, *xp, *yp, *wqkv, *wo;
    cudaGetSymbolAddress((void**)&qkv, g_qkv);
    cudaGetSymbolAddress((void**)&xp, g_xp);
    cudaGetSymbolAddress((void**)&yp, g_yp);
    cudaGetSymbolAddress((void**)&wqkv, g_wqkv);
    cudaGetSymbolAddress((void**)&wo, g_wo);

    cudaFuncSetAttribute(gemm_tf32p,
                         cudaFuncAttributeMaxDynamicSharedMemorySize, PG_SMEM);
    cudaFuncSetAttribute(band_gemm_p,
                         cudaFuncAttributeMaxDynamicSharedMemorySize, BAND_SMEM);

    // preps (independent)
    pack_a<<<(BT * 64) / 256, 256>>>(x, xp);
    pack_w<<<(98304 + 32768) / 256, 256>>>(Wq, Wk, Wv, Wo);
    build_cwP<<<768, 256>>>(w_bias);
    zero_uek_pad<<<(BB * 384 * 512) / (256 * 4), 256>>>();

    // fused QKV projection: [32768,256] x [256,768] (packed tf32)
    gemm_tf32p<<<dim3(6, BT / 128), 256, PG_SMEM>>>(xp, wqkv, qkv, QKV_LD);

    // elementwise + uek materialization + global sums
    ew_reduce<<<dim3(16, BB), 256>>>();
    reduce_final<<<BB, 512>>>();

    // banded num/den corrections (packed A, async, triangle skip)
    band_gemm_p<<<dim3(4, 16, BB), 256, BAND_SMEM>>>();

    // fused gating+pack, then output projection: [32768,256] x [256,256]
    pack_y<<<(BT * 64) / 256, 256>>>();
    gemm_tf32p<<<dim3(2, BT / 128), 256, PG_SMEM>>>(yp, wo, out, DD);
}

// round 14
// speedup vs baseline: 2.0361x; 1.4336x over previous
#include <cuda_runtime.h>
#include <cuda_bf16.h>
#include <cstddef>
#include <cstdint>

// Problem constants (B=16, T=2048, D=256, WINDOW=128)
#define BB 16
#define TT 2048
#define DD 256
#define WIN 128
#define BT (BB*TT)          // 32768
#define PADT 2432

// ---------------- scratch (__device__ globals; no allocation) ---------------
__device__ float g_q[(size_t)BT * 256];          // raw q, row-major
__device__ float g_cwP[(size_t)16 * 12 * 4096];  // band A, packed fragment order
__device__ float g_uek[(size_t)BB * PADT * 512]; // interleaved [b][s+128][(u,ek) x 256d]
__device__ float g_Spart[(size_t)512 * 512];     // [mblk*2+wm][(su,se) x 256d]
__device__ float g_S[(size_t)BB * 512];          // [b][(Su,Se) x 256d]

__device__ float g_xp[(size_t)BT * 256];         // x, packed fragment order
__device__ float g_yp[(size_t)BT * 256];         // y, packed fragment order
__device__ float g_wqkv[(size_t)256 * 768];      // packed W: q | interleaved (k,v)
__device__ float g_wo[(size_t)256 * 256];        // packed Wo

// ---------------- helpers ---------------------------------------------------
__device__ __forceinline__ float to_tf32(float v) {
    float r;
    asm("cvt.rna.tf32.f32 %0, %1;" : "=f"(r) : "f"(v));
    return r;
}
__device__ __forceinline__ uint32_t smem_u32(const void* p) {
    return (uint32_t)__cvta_generic_to_shared(p);
}
#define CP16(dst, src) \
    asm volatile("cp.async.cg.shared.global [%0], [%1], 16;" :: "r"(dst), "l"(src))

// ---------------- operand packing -------------------------------------------
// A packed: region(mblk, kc) = 4096 floats; [(kk*8+mi)*32+lane]*4 =
// {A[r][c], A[r+8][c], A[r][c+4], A[r+8][c+4]}.
__global__ void pack_a(const float* __restrict__ src, float* __restrict__ dst)
{
    int fid = blockIdx.x * 256 + threadIdx.x;
    int rg = fid >> 10;
    int q  = fid & 1023;
    int slot = q >> 5;
    int lane = q & 31;
    int mblk = rg >> 3, kc = rg & 7;
    int kk = slot >> 3, mi = slot & 7;
    int quad = lane >> 2, qt = lane & 3;
    int r0 = mblk * 128 + mi * 16 + quad;
    int c0 = kc * 32 + kk * 8 + qt;
    const float* s = src + (size_t)r0 * 256 + c0;
    float4 v;
    v.x = to_tf32(s[0]);
    v.y = to_tf32(s[8 * 256]);
    v.z = to_tf32(s[4]);
    v.w = to_tf32(s[8 * 256 + 4]);
    *(float4*)&dst[(size_t)fid * 4] = v;
}

// Packed W cols: n<256 -> Wq_n; n>=256 -> even: Wk_{(n-256)/2}, odd: Wv
__global__ void pack_w(const float* __restrict__ Wq, const float* __restrict__ Wk,
                       const float* __restrict__ Wv, const float* __restrict__ Wo)
{
    int f2 = blockIdx.x * 256 + threadIdx.x;
    bool isO = f2 >= 98304;
    int base = isO ? (f2 - 98304) : f2;
    int rg = base >> 11;
    int q  = base & 2047;
    int slot = q >> 5;
    int lane = q & 31;
    int nblk = rg >> 3, kc = rg & 7;
    int kk = slot >> 4, nj = slot & 15;
    int quad = lane >> 2, qt = lane & 3;
    int k0 = kc * 32 + kk * 8 + qt;
    int n = nblk * 128 + nj * 8 + quad;
    float v0, v1;
    if (isO) {
        v0 = Wo[(size_t)k0 * 256 + n];
        v1 = Wo[(size_t)(k0 + 4) * 256 + n];
    } else {
        const float* W; int nn;
        if (n < 256) { W = Wq; nn = n; }
        else { int np = n - 256; W = (np & 1) ? Wv : Wk; nn = np >> 1; }
        v0 = W[(size_t)k0 * 256 + nn];
        v1 = W[(size_t)(k0 + 4) * 256 + nn];
    }
    float* dst = isO ? g_wo : g_wqkv;
    *(float2*)&dst[(size_t)base * 2] = make_float2(to_tf32(v0), to_tf32(v1));
}

// ---------------- mma macros ------------------------------------------------
#define MMA_TF32V(d, a, b) \
    asm volatile("mma.sync.aligned.m16n8k8.row.col.f32.tf32.tf32.f32 " \
                 "{%0,%1,%2,%3},{%4,%5,%6,%7},{%8,%9},{%0,%1,%2,%3};" \
                 : "+f"(d[0]), "+f"(d[1]), "+f"(d[2]), "+f"(d[3]) \
                 : "r"(a.x), "r"(a.y), "r"(a.z), "r"(a.w), "r"(b.x), "r"(b.y))

#define MMA_TF32S(d, a, b0, b1) \
    asm volatile("mma.sync.aligned.m16n8k8.row.col.f32.tf32.tf32.f32 " \
                 "{%0,%1,%2,%3},{%4,%5,%6,%7},{%8,%9},{%0,%1,%2,%3};" \
                 : "+f"(d[0]), "+f"(d[1]), "+f"(d[2]), "+f"(d[3]) \
                 : "r"(a.x), "r"(a.y), "r"(a.z), "r"(a.w), "r"(b0), "r"(b1))

#define PG_SMEM (2 * 8192 * 4)

// ---------------- shared GEMM mainloop (packed operands) --------------------
#define GEMM_MAINLOOP(Abase, Bbase)                                              \
    {                                                                            \
        float* dA = sm; float* dB = sm + 4096;                                   \
        _Pragma("unroll")                                                        \
        for (int r = 0; r < 4; r++) {                                            \
            CP16(smem_u32(dA + (r * 256 + tid) * 4), Abase + (size_t)(r * 256 + tid) * 4); \
            CP16(smem_u32(dB + (r * 256 + tid) * 4), Bbase + (size_t)(r * 256 + tid) * 4); \
        }                                                                        \
        asm volatile("cp.async.commit_group;");                                  \
    }                                                                            \
    int stage = 0;                                                               \
    for (int c = 0; c < 8; c++) {                                                \
        if (c < 7) {                                                             \
            float* dA = sm + (stage ^ 1) * 8192;                                 \
            float* dB = dA + 4096;                                               \
            const float* gA = Abase + (size_t)(c + 1) * 4096;                    \
            const float* gB = Bbase + (size_t)(c + 1) * 4096;                    \
            _Pragma("unroll")                                                    \
            for (int r = 0; r < 4; r++) {                                        \
                CP16(smem_u32(dA + (r * 256 + tid) * 4), gA + (size_t)(r * 256 + tid) * 4); \
                CP16(smem_u32(dB + (r * 256 + tid) * 4), gB + (size_t)(r * 256 + tid) * 4); \
            }                                                                    \
            asm volatile("cp.async.commit_group;");                              \
            asm volatile("cp.async.wait_group 1;");                              \
        } else {                                                                 \
            asm volatile("cp.async.wait_group 0;");                              \
        }                                                                        \
        __syncthreads();                                                         \
        const float* A = sm + stage * 8192;                                      \
        const float* B = A + 4096;                                               \
        _Pragma("unroll")                                                        \
        for (int kk = 0; kk < 4; kk++) {                                         \
            uint4 af[4];                                                         \
            uint2 bf[4];                                                         \
            _Pragma("unroll")                                                    \
            for (int i = 0; i < 4; i++)                                          \
                af[i] = *(const uint4*)&A[(kk * 8 + wm * 4 + i) * 128 + lane * 4]; \
            _Pragma("unroll")                                                    \
            for (int j = 0; j < 4; j++)                                          \
                bf[j] = *(const uint2*)&B[(kk * 16 + wn * 4 + j) * 64 + lane * 2]; \
            _Pragma("unroll")                                                    \
            for (int i = 0; i < 4; i++)                                          \
                _Pragma("unroll")                                                \
                for (int j = 0; j < 4; j++) MMA_TF32V(acc[i][j], af[i], bf[j]);  \
        }                                                                        \
        __syncthreads();                                                         \
        stage ^= 1;                                                              \
    }

// ---------------- plain packed GEMM (output projection) ---------------------
__global__ void __launch_bounds__(256, 2) gemm_tf32p(
    const float* __restrict__ Ap, const float* __restrict__ Bp,
    float* __restrict__ C, int ldc)
{
    extern __shared__ float sm[];
    const int tid = threadIdx.x;
    const int nblk = blockIdx.x;
    const int mblk = blockIdx.y;
    const float* Abase = Ap + (size_t)mblk * 8 * 4096;
    const float* Bbase = Bp + (size_t)nblk * 8 * 4096;
    const int lane = tid & 31, w = tid >> 5;
    const int wm = w & 1, wn = w >> 1;
    const int quad = lane >> 2, qt = lane & 3;

    float acc[4][4][4];
#pragma unroll
    for (int i = 0; i < 4; i++)
#pragma unroll
        for (int j = 0; j < 4; j++)
#pragma unroll
            for (int e = 0; e < 4; e++) acc[i][j][e] = 0.f;

    GEMM_MAINLOOP(Abase, Bbase)

#pragma unroll
    for (int i = 0; i < 4; i++) {
#pragma unroll
        for (int j = 0; j < 4; j++) {
            int r = mblk * 128 + wm * 64 + i * 16 + quad;
            int cc = nblk * 128 + wn * 32 + j * 8 + qt * 2;
            *(float2*)&C[(size_t)r * ldc + cc] = make_float2(acc[i][j][0], acc[i][j][1]);
            *(float2*)&C[(size_t)(r + 8) * ldc + cc] = make_float2(acc[i][j][2], acc[i][j][3]);
        }
    }
}

// ---------------- QKV GEMM with fused elementwise epilogue ------------------
__global__ void __launch_bounds__(256, 2) gemm_qkv(
    const float* __restrict__ Ap, const float* __restrict__ Bp)
{
    extern __shared__ float sm[];
    const int tid = threadIdx.x;
    const int nblk = blockIdx.x;     // 0..5
    const int mblk = blockIdx.y;     // 0..255
    const float* Abase = Ap + (size_t)mblk * 8 * 4096;
    const float* Bbase = Bp + (size_t)nblk * 8 * 4096;
    const int lane = tid & 31, w = tid >> 5;
    const int wm = w & 1, wn = w >> 1;
    const int quad = lane >> 2, qt = lane & 3;

    float acc[4][4][4];
#pragma unroll
    for (int i = 0; i < 4; i++)
#pragma unroll
        for (int j = 0; j < 4; j++)
#pragma unroll
            for (int e = 0; e < 4; e++) acc[i][j][e] = 0.f;

    GEMM_MAINLOOP(Abase, Bbase)

    if (nblk < 2) {
        // q columns: store raw q row-major
#pragma unroll
        for (int i = 0; i < 4; i++) {
#pragma unroll
            for (int j = 0; j < 4; j++) {
                int r = mblk * 128 + wm * 64 + i * 16 + quad;
                int cc = nblk * 128 + wn * 32 + j * 8 + qt * 2;
                *(float2*)&g_q[(size_t)r * 256 + cc] = make_float2(acc[i][j][0], acc[i][j][1]);
                *(float2*)&g_q[(size_t)(r + 8) * 256 + cc] = make_float2(acc[i][j][2], acc[i][j][3]);
            }
        }
    } else {
        // interleaved (k,v) columns: compute ek, u; write uek; partial sums
        const int b = mblk >> 4;
        const int trow0 = (mblk & 15) * 128 + wm * 64;
        float su[4] = {0.f, 0.f, 0.f, 0.f};
        float se[4] = {0.f, 0.f, 0.f, 0.f};
#pragma unroll
        for (int i = 0; i < 4; i++) {
            int t = trow0 + i * 16 + quad;
            size_t ur = ((size_t)b * PADT + t + 128) * 512;
#pragma unroll
            for (int j = 0; j < 4; j++) {
                int d = (nblk - 2) * 64 + wn * 16 + j * 4 + qt;
                float ek0 = expf(acc[i][j][0]);
                float u0  = ek0 * acc[i][j][1];
                float ek8 = expf(acc[i][j][2]);
                float u8  = ek8 * acc[i][j][3];
                *(float2*)&g_uek[ur + 2 * d] =
                    make_float2(to_tf32(u0), to_tf32(ek0));
                *(float2*)&g_uek[ur + 8 * 512 + 2 * d] =
                    make_float2(to_tf32(u8), to_tf32(ek8));
                su[j] += u0 + u8;
                se[j] += ek0 + ek8;
            }
        }
#pragma unroll
        for (int off = 4; off < 32; off <<= 1) {
#pragma unroll
            for (int j = 0; j < 4; j++) {
                su[j] += __shfl_xor_sync(0xffffffffu, su[j], off);
                se[j] += __shfl_xor_sync(0xffffffffu, se[j], off);
            }
        }
        if (quad == 0) {
#pragma unroll
            for (int j = 0; j < 4; j++) {
                int d = (nblk - 2) * 64 + wn * 16 + j * 4 + qt;
                size_t s = ((size_t)mblk * 2 + wm) * 512 + 2 * d;
                g_Spart[s]     = su[j];
                g_Spart[s + 1] = se[j];
            }
        }
    }
}

// ---------------- band A, packed fragment order -----------------------------
__device__ __forceinline__ float cw_val(const float* wb, int t, int t0, int j)
{
    int s = t0 - 128 + j;
    int dlt = t - s;
    if (s < 0 || s >= TT || dlt >= WIN || dlt <= -WIN) return 0.f;
    return to_tf32(expf(wb[(size_t)t * TT + s]) - 1.f);
}

__global__ void build_cwP(const float* __restrict__ wb)
{
    int fid = blockIdx.x * 256 + threadIdx.x;
    int rg = fid >> 10;
    int q  = fid & 1023;
    int slot = q >> 5;
    int lane = q & 31;
    int tile = rg / 12, kc = rg - tile * 12;
    int kk = slot >> 3, mi = slot & 7;
    int quad = lane >> 2, qt = lane & 3;
    int t0 = tile * 128;
    int t = t0 + mi * 16 + quad;
    int j = kc * 32 + kk * 8 + qt;
    float4 v;
    v.x = cw_val(wb, t,     t0, j);
    v.y = cw_val(wb, t + 8, t0, j);
    v.z = cw_val(wb, t,     t0, j + 4);
    v.w = cw_val(wb, t + 8, t0, j + 4);
    *(float4*)&g_cwP[(size_t)fid * 4] = v;
}

__global__ void zero_uek_pad()
{
    size_t i = (size_t)blockIdx.x * 256 + threadIdx.x;
    size_t e = i * 4;
    int b = e / (384 * 512);
    int rem = e % (384 * 512);
    int r = rem / 512;
    int c = rem % 512;
    int p = (r < 128) ? r : (r + 2048);
    *(float4*)&g_uek[((size_t)b * PADT + p) * 512 + c] = make_float4(0.f, 0.f, 0.f, 0.f);
}

__global__ void reduce_final()
{
    int b = blockIdx.x;
    int i = threadIdx.x;
    float acc = 0.f;
    for (int j = 0; j < 32; j++)
        acc += g_Spart[((size_t)(b * 32 + j)) * 512 + i];
    g_S[(size_t)b * 512 + i] = acc;
}

// ---------------- band GEMM with fused gating + y-pack epilogue -------------
#define SPB 136
#define BSM_A 4096
#define BSM_B (32 * SPB)
#define BSTG (BSM_A + BSM_B)
#define BAND_SMEM (2 * BSTG * 4)

__global__ void __launch_bounds__(256, 2) band_gemm_f()
{
    extern __shared__ float bsm[];
    const int tid = threadIdx.x;
    const int nblk = blockIdx.x;     // 0..3
    const int tile = blockIdx.y;     // 0..15
    const int b    = blockIdx.z;
    const int t0 = tile * 128;
    const int n0 = nblk * 128;

    const float* Ap = g_cwP + (size_t)tile * 12 * 4096;
    const float* Bg = g_uek + (size_t)b * PADT * 512;

    const int lane = tid & 31, w = tid >> 5;
    const int wm = w & 1, wn = w >> 1;
    const int quad = lane >> 2, qt = lane & 3;
    const int brow = tid >> 3;
    const int bcol = (tid & 7) * 16;

    float acc[4][4][4];
#pragma unroll
    for (int i = 0; i < 4; i++)
#pragma unroll
        for (int j = 0; j < 4; j++)
#pragma unroll
            for (int e = 0; e < 4; e++) acc[i][j][e] = 0.f;

    auto issue = [&](int stg, int c) {
        float* sA = bsm + stg * BSTG;
        float* sB = sA + BSM_A;
        const float* gA = Ap + (size_t)c * 4096;
#pragma unroll
        for (int r = 0; r < 4; r++)
            CP16(smem_u32(sA + (r * 256 + tid) * 4), gA + (size_t)(r * 256 + tid) * 4);
        const float* bp = Bg + (size_t)(t0 + c * 32 + brow) * 512 + n0 + bcol;
        float* dst = sB + brow * SPB + bcol;
#pragma unroll
        for (int s = 0; s < 4; s++)
            CP16(smem_u32(dst + s * 4), bp + s * 4);
        asm volatile("cp.async.commit_group;");
    };

    issue(0, 0);
    int stage = 0;
    for (int c = 0; c < 12; c++) {
        if (c < 11) {
            issue(stage ^ 1, c + 1);
            asm volatile("cp.async.wait_group 1;");
        } else {
            asm volatile("cp.async.wait_group 0;");
        }
        __syncthreads();

        const float* A = bsm + stage * BSTG;
        const float* B = A + BSM_A;
        const int tbw = wm * 64;
#pragma unroll
        for (int kk = 0; kk < 4; kk++) {
            int jb = c * 32 + kk * 8;
            if (jb >= tbw - 6 && jb <= tbw + 318) {
                uint32_t b0[4], b1[4];
#pragma unroll
                for (int j = 0; j < 4; j++) {
                    int n = wn * 32 + j * 8 + quad;
                    b0[j] = *(const uint32_t*)&B[(kk * 8 + qt) * SPB + n];
                    b1[j] = *(const uint32_t*)&B[(kk * 8 + qt + 4) * SPB + n];
                }
#pragma unroll
                for (int i = 0; i < 4; i++) {
                    int tb = tbw + i * 16;
                    if (jb >= tb - 6 && jb <= tb + 270) {
                        uint4 af = *(const uint4*)&A[(kk * 8 + wm * 4 + i) * 128 + lane * 4];
#pragma unroll
                        for (int j = 0; j < 4; j++)
                            MMA_TF32S(acc[i][j], af, b0[j], b1[j]);
                    }
                }
            }
        }
        __syncthreads();
        stage ^= 1;
    }

    // fused epilogue: y = sigmoid(q) * (Su+num)/(Se+den), packed into g_yp
    const int mblk_y = b * 16 + tile;
#pragma unroll
    for (int i = 0; i < 4; i++) {
        int trow = t0 + wm * 64 + i * 16 + quad;
        size_t qrow = (size_t)(b * TT + trow) * 256;
        int mi = wm * 4 + i;
        float y0[4], y8[4];
#pragma unroll
        for (int j = 0; j < 4; j++) {
            int d = (n0 >> 1) + wn * 16 + j * 4 + qt;
            float2 S = *(const float2*)&g_S[(size_t)b * 512 + 2 * d];
            float q0 = g_q[qrow + d];
            float q8 = g_q[qrow + 8 * 256 + d];
            float sg0 = 1.f / (1.f + expf(-q0));
            float sg8 = 1.f / (1.f + expf(-q8));
            y0[j] = to_tf32(sg0 * (S.x + acc[i][j][0]) / (S.y + acc[i][j][1]));
            y8[j] = to_tf32(sg8 * (S.x + acc[i][j][2]) / (S.y + acc[i][j][3]));
        }
#pragma unroll
        for (int j0 = 0; j0 < 4; j0 += 2) {
            int c0 = (n0 >> 1) + wn * 16 + j0 * 4 + qt;
            int kc = c0 >> 5;
            int kk = (c0 >> 3) & 3;
            int slot = kk * 8 + mi;
            size_t off = (((size_t)(mblk_y * 8 + kc) * 32 + slot) * 32 + lane) * 4;
            *(float4*)&g_yp[off] = make_float4(y0[j0], y8[j0], y0[j0 + 1], y8[j0 + 1]);
        }
    }
}

// ---------------- launch ----------------------------------------------------
extern "C" void kernel_launch(void* const* d_in, const int* in_sizes, int n_in,
                              void* d_out, int out_size)
{
    const float* x      = (const float*)d_in[0];
    const float* Wq     = (const float*)d_in[1];
    const float* Wk     = (const float*)d_in[2];
    const float* Wv     = (const float*)d_in[3];
    const float* Wo     = (const float*)d_in[4];
    const float* w_bias = (const float*)d_in[5];
    float* out = (float*)d_out;

    float *xp, *yp, *wqkv, *wo;
    cudaGetSymbolAddress((void**)&xp, g_xp);
    cudaGetSymbolAddress((void**)&yp, g_yp);
    cudaGetSymbolAddress((void**)&wqkv, g_wqkv);
    cudaGetSymbolAddress((void**)&wo, g_wo);

    cudaFuncSetAttribute(gemm_tf32p,
                         cudaFuncAttributeMaxDynamicSharedMemorySize, PG_SMEM);
    cudaFuncSetAttribute(gemm_qkv,
                         cudaFuncAttributeMaxDynamicSharedMemorySize, PG_SMEM);
    cudaFuncSetAttribute(band_gemm_f,
                         cudaFuncAttributeMaxDynamicSharedMemorySize, BAND_SMEM);

    // preps (independent)
    pack_a<<<(BT * 64) / 256, 256>>>(x, xp);
    pack_w<<<(98304 + 32768) / 256, 256>>>(Wq, Wk, Wv, Wo);
    build_cwP<<<768, 256>>>(w_bias);
    zero_uek_pad<<<(BB * 384 * 512) / (256 * 4), 256>>>();

    // QKV projection + fused elementwise/uek/partial-sum epilogue
    gemm_qkv<<<dim3(6, BT / 128), 256, PG_SMEM>>>(xp, wqkv);

    // finish global sums
    reduce_final<<<BB, 512>>>();

    // band GEMM + fused gating + fragment-packed y
    band_gemm_f<<<dim3(4, 16, BB), 256, BAND_SMEM>>>();

    // output projection: [32768,256] x [256,256]
    gemm_tf32p<<<dim3(2, BT / 128), 256, PG_SMEM>>>(yp, wo, out, DD);
}